// round 8
// baseline (speedup 1.0000x reference)
#include <cuda_runtime.h>
#include <cstdint>

#define T_STEPS 20
#define HID     128
#define BATCH   65536
#define M_TILE  64
#define THREADS 256
#define MST     68                       // m-stride of transposed h buffer

// Shared memory layout (floats)
#define OFF_W    0                       // 2 bufs x [4][32][128] = 32768
#define OFF_G    16384                   // gate exchange region = weight buf1 (aliased)
#define OFF_H    32768                   // hT [128][MST] = 8704
#define OFF_OBS  (OFF_H + 128 * MST)     // [20][2][64] = 2560
#define OFF_WC   (OFF_OBS + 2560)        // [2][512]
#define OFF_BC   (OFF_WC + 1024)         // [512]
#define SMEM_FLOATS (OFF_BC + 512)       // 45568
#define SMEM_BYTES  (SMEM_FLOATS * 4)    // 182272 bytes

__device__ __align__(16) float g_Wt[4][128][128]; // [gate][k][d] = W_hh[(g*128+d)*128+k]
__device__ __align__(16) float g_Wc[2][512];      // combined obs->gate weights
__device__ __align__(16) float g_bc[512];         // combined bias

typedef unsigned long long u64t;

__device__ __forceinline__ u64t fma2(u64t a, u64t b, u64t c) {
    u64t d;
    asm("fma.rn.f32x2 %0, %1, %2, %3;" : "=l"(d) : "l"(a), "l"(b), "l"(c));
    return d;
}
__device__ __forceinline__ u64t pack2(float x) {
    u64t d;
    asm("mov.b64 %0, {%1, %1};" : "=l"(d) : "f"(x));
    return d;
}
__device__ __forceinline__ void unpack2(u64t v, float& lo, float& hi) {
    asm("mov.b64 {%0, %1}, %2;" : "=f"(lo), "=f"(hi) : "l"(v));
}

__device__ __forceinline__ void cp16(void* dst_smem, const void* src) {
    uint32_t d = (uint32_t)__cvta_generic_to_shared(dst_smem);
    asm volatile("cp.async.cg.shared.global [%0], [%1], 16;" :: "r"(d), "l"(src));
}
#define CP_COMMIT() asm volatile("cp.async.commit_group;" ::: "memory")
#define CP_WAIT1()  asm volatile("cp.async.wait_group 1;"  ::: "memory")
#define CP_WAIT0()  asm volatile("cp.async.wait_group 0;"  ::: "memory")

__device__ __forceinline__ float fsig(float x) {
    float e = __expf(-x);
    return __fdividef(1.0f, 1.0f + e);
}
__device__ __forceinline__ float ftanh(float x) {
    x = fminf(fmaxf(x, -15.0f), 15.0f);
    float e = __expf(-2.0f * x);
    return __fdividef(1.0f - e, 1.0f + e);
}

// ---------------------------------------------------------------------------
// Setup: fold embedding into gate weights; transpose W_hh per gate (k-major).
// ---------------------------------------------------------------------------
__global__ void setup_kernel(const float* __restrict__ W_emb, const float* __restrict__ b_emb,
                             const float* __restrict__ W_ih,  const float* __restrict__ W_hh,
                             const float* __restrict__ b_ih,  const float* __restrict__ b_hh) {
    int gid = blockIdx.x * blockDim.x + threadIdx.x;
    if (gid < 4 * 128 * 128) {
        int g = gid >> 14;
        int k = (gid >> 7) & 127;
        int d = gid & 127;
        g_Wt[g][k][d] = W_hh[(g * 128 + d) * 128 + k];
    }
    if (gid < 512) {
        float w0 = 0.f, w1 = 0.f, bb = 0.f;
        #pragma unroll 8
        for (int j = 0; j < 64; ++j) {
            float wij = W_ih[gid * 64 + j];
            w0 += wij * W_emb[j * 2 + 0];
            w1 += wij * W_emb[j * 2 + 1];
            bb += wij * b_emb[j];
        }
        g_Wc[0][gid] = w0;
        g_Wc[1][gid] = w1;
        g_bc[gid]    = bb + b_ih[gid] + b_hh[gid];
    }
}

// ---------------------------------------------------------------------------
// Main fused LSTM kernel (warp-per-gate layout).
// 8 warps: gate = wid>>1, m-half = wid&1 (32 m rows each), lanes own d=4*lid+j.
// Per k: 1 weight LDS.128 reused over 32 m (4x less weight crossbar traffic),
// h read as natural m-pairs for fma.f32x2 (no h-side MOVs).
// Gates exchanged via smem (reusing free weight buf1) in two m-half passes;
// c in registers (ownership: warp wid updates m = 8*wid..8*wid+7).
// ---------------------------------------------------------------------------
__global__ void __launch_bounds__(THREADS, 1)
lstm_kernel(const float* __restrict__ obs, const float* __restrict__ h0,
            const float* __restrict__ c0, float* __restrict__ out) {
    extern __shared__ float smem[];
    float* sW   = smem + OFF_W;
    float* sG   = smem + OFF_G;     // alias of weight buffer 1
    float* sH   = smem + OFF_H;     // [128][MST] transposed h (single buffer)
    float* sObs = smem + OFF_OBS;   // [20][2][64]
    float* sWc  = smem + OFF_WC;
    float* sBc  = smem + OFF_BC;

    const int tid   = threadIdx.x;
    const int lid   = tid & 31;
    const int wid   = tid >> 5;
    const int g     = wid >> 1;       // gate this warp computes
    const int mOff  = (wid & 1) * 32; // m-half this warp computes
    const int mBase = blockIdx.x * M_TILE;

    // --- Stage h0 (transposed), obs (transposed [t][c][m]), combined W/bias ---
    for (int idx = tid; idx < M_TILE * HID; idx += THREADS) {
        int m = idx >> 7, d = idx & 127;
        sH[d * MST + m] = h0[(size_t)(mBase + m) * HID + d];
    }
    for (int idx = tid; idx < T_STEPS * 128; idx += THREADS) {
        int t = idx >> 7, r = idx & 127;
        int c = r >> 6, m = r & 63;
        sObs[idx] = obs[((size_t)t * BATCH + mBase + m) * 2 + c];
    }
    for (int idx = tid; idx < 1024; idx += THREADS) sWc[idx] = (&g_Wc[0][0])[idx];
    for (int idx = tid; idx < 512;  idx += THREADS) sBc[idx] = g_bc[idx];

    // --- c0 into registers: cc[mi][j] for m = 8*wid+mi, d = 4*lid+j ---
    float cc[8][4];
    #pragma unroll
    for (int mi = 0; mi < 8; ++mi) {
        float4 a = *(const float4*)&c0[(size_t)(mBase + 8 * wid + mi) * HID + 4 * lid];
        cc[mi][0] = a.x; cc[mi][1] = a.y; cc[mi][2] = a.z; cc[mi][3] = a.w;
    }

    // --- Prefetch window 0 (k 0..31, all 4 gates) into buf 0 ---
    #pragma unroll
    for (int i = 0; i < 16; ++i) {
        int lin = tid + i * 256;
        int g2 = lin >> 10, rem = lin & 1023;
        int kk = rem >> 5, dq = rem & 31;
        cp16(sW + g2 * 4096 + kk * 128 + dq * 4, &g_Wt[g2][kk][dq * 4]);
    }
    CP_COMMIT();
    __syncthreads();

    u64t acc[64];   // [mp 0..15][j 0..3]: pair = (m=mOff+2mp, m+1), d = 4*lid+j

    for (int t = 0; t < T_STEPS; ++t) {
        // --- init gates: bias + 2-wide obs projection (folded embedding) ---
        {
            float4 wa = *(const float4*)&sWc[g * 128 + 4 * lid];
            float4 wb = *(const float4*)&sWc[512 + g * 128 + 4 * lid];
            float4 bv = *(const float4*)&sBc[g * 128 + 4 * lid];
            u64t wdA[4] = {pack2(wa.x), pack2(wa.y), pack2(wa.z), pack2(wa.w)};
            u64t wdB[4] = {pack2(wb.x), pack2(wb.y), pack2(wb.z), pack2(wb.w)};
            u64t bd [4] = {pack2(bv.x), pack2(bv.y), pack2(bv.z), pack2(bv.w)};
            const float* ob0 = sObs + (t * 2 + 0) * 64 + mOff;
            const float* ob1 = sObs + (t * 2 + 1) * 64 + mOff;
            #pragma unroll
            for (int mp = 0; mp < 16; ++mp) {
                u64t o0 = *(const u64t*)(ob0 + 2 * mp);
                u64t o1 = *(const u64t*)(ob1 + 2 * mp);
                #pragma unroll
                for (int j = 0; j < 4; ++j)
                    acc[mp * 4 + j] = fma2(o1, wdB[j], fma2(o0, wdA[j], bd[j]));
            }
        }

        // --- recurrent GEMM: 4 windows of 32 k, double-buffered weights ---
        int buf = 0;
        #pragma unroll 1
        for (int w = 0; w < 4; ++w) {
            __syncthreads();   // prev compute / elementwise done -> dest buf free
            {
                int nw = (w + 1) & 3;     // at w=3 prefetch window 0 for next step
                float* dst = sW + (buf ^ 1) * 16384;
                #pragma unroll
                for (int i = 0; i < 16; ++i) {
                    int lin = tid + i * 256;
                    int g2 = lin >> 10, rem = lin & 1023;
                    int kk = rem >> 5, dq = rem & 31;
                    cp16(dst + g2 * 4096 + kk * 128 + dq * 4,
                         &g_Wt[g2][nw * 32 + kk][dq * 4]);
                }
                CP_COMMIT();
                CP_WAIT1();    // this window's group complete (own thread)
            }
            __syncthreads();   // all threads' cp for this window visible

            const float* wbp = sW + buf * 16384 + g * 4096;
            const float* hbs = sH + (w * 32) * MST + mOff;
            #pragma unroll 4
            for (int kk = 0; kk < 32; ++kk) {
                const float* hrow = hbs + kk * MST;
                u64t hp[16];
                #pragma unroll
                for (int i = 0; i < 8; ++i) {
                    ulonglong2 q = *(const ulonglong2*)(hrow + 4 * i);
                    hp[2 * i] = q.x; hp[2 * i + 1] = q.y;
                }
                float4 wv = *(const float4*)(wbp + kk * 128 + 4 * lid);
                u64t w0 = pack2(wv.x), w1 = pack2(wv.y), w2 = pack2(wv.z), w3 = pack2(wv.w);
                #pragma unroll
                for (int mp = 0; mp < 16; ++mp) {
                    acc[mp * 4 + 0] = fma2(hp[mp], w0, acc[mp * 4 + 0]);
                    acc[mp * 4 + 1] = fma2(hp[mp], w1, acc[mp * 4 + 1]);
                    acc[mp * 4 + 2] = fma2(hp[mp], w2, acc[mp * 4 + 2]);
                    acc[mp * 4 + 3] = fma2(hp[mp], w3, acc[mp * 4 + 3]);
                }
            }
            buf ^= 1;
        }

        // --- gate exchange + cell update, two m-half passes through sG (=buf1;
        //     buf1 is free: window 3 consumed it, next prefetch targets buf0) ---
        #pragma unroll 1
        for (int p = 0; p < 2; ++p) {
            __syncthreads();   // p=0: all GEMM reads of sH/buf1 done; p=1: pass-0 reads of sG done
            if ((wid & 1) == p) {
                float* dst = sG + g * 4096 + 4 * lid;
                #pragma unroll
                for (int mp = 0; mp < 16; ++mp) {
                    float l0, h0_, l1, h1_, l2, h2_, l3, h3_;
                    unpack2(acc[mp * 4 + 0], l0, h0_);
                    unpack2(acc[mp * 4 + 1], l1, h1_);
                    unpack2(acc[mp * 4 + 2], l2, h2_);
                    unpack2(acc[mp * 4 + 3], l3, h3_);
                    *(float4*)(dst + (2 * mp) * 128)     = make_float4(l0, l1, l2, l3);
                    *(float4*)(dst + (2 * mp + 1) * 128) = make_float4(h0_, h1_, h2_, h3_);
                }
            }
            __syncthreads();
            if ((wid >> 2) == p) {   // warps owning m = 8*wid.. in [32p, 32p+32)
                int widp = wid - 4 * p;
                float hv[8][4];
                #pragma unroll
                for (int mi = 0; mi < 8; ++mi) {
                    const float* gp = sG + (widp * 8 + mi) * 128 + 4 * lid;
                    float4 iv = *(const float4*)(gp + 0 * 4096);
                    float4 fv = *(const float4*)(gp + 1 * 4096);
                    float4 gv = *(const float4*)(gp + 2 * 4096);
                    float4 ov = *(const float4*)(gp + 3 * 4096);
                    float cn;
                    cn = fsig(fv.x) * cc[mi][0] + fsig(iv.x) * ftanh(gv.x);
                    cc[mi][0] = cn; hv[mi][0] = fsig(ov.x) * ftanh(cn);
                    cn = fsig(fv.y) * cc[mi][1] + fsig(iv.y) * ftanh(gv.y);
                    cc[mi][1] = cn; hv[mi][1] = fsig(ov.y) * ftanh(cn);
                    cn = fsig(fv.z) * cc[mi][2] + fsig(iv.z) * ftanh(gv.z);
                    cc[mi][2] = cn; hv[mi][2] = fsig(ov.z) * ftanh(cn);
                    cn = fsig(fv.w) * cc[mi][3] + fsig(iv.w) * ftanh(gv.w);
                    cc[mi][3] = cn; hv[mi][3] = fsig(ov.w) * ftanh(cn);
                }
                #pragma unroll
                for (int j = 0; j < 4; ++j) {
                    int d = 4 * lid + j;
                    *(float4*)(sH + d * MST + 8 * wid) =
                        make_float4(hv[0][j], hv[1][j], hv[2][j], hv[3][j]);
                    *(float4*)(sH + d * MST + 8 * wid + 4) =
                        make_float4(hv[4][j], hv[5][j], hv[6][j], hv[7][j]);
                }
            }
        }
        // next step: w-loop's first __syncthreads orders h writes before reads
    }

    CP_WAIT0();
    __syncthreads();

    // --- write final h (coalesced along d) ---
    for (int idx = tid; idx < M_TILE * HID; idx += THREADS) {
        int m = idx >> 7, d = idx & 127;
        out[(size_t)(mBase + m) * HID + d] = sH[d * MST + m];
    }
}

extern "C" void kernel_launch(void* const* d_in, const int* in_sizes, int n_in,
                              void* d_out, int out_size) {
    const float* obs   = (const float*)d_in[0];
    const float* h0    = (const float*)d_in[1];
    const float* c0    = (const float*)d_in[2];
    const float* W_emb = (const float*)d_in[3];
    const float* b_emb = (const float*)d_in[4];
    const float* W_ih  = (const float*)d_in[5];
    const float* W_hh  = (const float*)d_in[6];
    const float* b_ih  = (const float*)d_in[7];
    const float* b_hh  = (const float*)d_in[8];
    float* out = (float*)d_out;

    (void)in_sizes; (void)n_in; (void)out_size;

    setup_kernel<<<256, 256>>>(W_emb, b_emb, W_ih, W_hh, b_ih, b_hh);

    cudaFuncSetAttribute(lstm_kernel, cudaFuncAttributeMaxDynamicSharedMemorySize, SMEM_BYTES);
    lstm_kernel<<<BATCH / M_TILE, THREADS, SMEM_BYTES>>>(obs, h0, c0, out);
}

// round 10
// speedup vs baseline: 1.1808x; 1.1808x over previous
#include <cuda_runtime.h>
#include <cstdint>

#define T_STEPS 20
#define HID     128
#define BATCH   65536
#define M_TILE  64
#define THREADS 256
#define HPAD    68            // padded m-stride of transposed h buffer
#define HBUF    (128 * HPAD)  // 8704 floats per h buffer

// Shared memory layout (floats)
#define OFF_W    0
#define OFF_H    (OFF_W + 2 * 16384)          // 32768
#define OFF_OBS  (OFF_H + 2 * HBUF)           // 50176
#define OFF_WC   (OFF_OBS + T_STEPS * 128)    // 52736
#define OFF_BC   (OFF_WC + 1024)              // 53760
#define SMEM_FLOATS (OFF_BC + 512)            // 54272
#define SMEM_BYTES  (SMEM_FLOATS * 4)         // 217088 bytes

// Precomputed weights (device scratch; no runtime allocation allowed)
__device__ __align__(16) float g_Wt[4][128][128]; // [gate][k][d] = W_hh[(g*128+d)*128+k]
__device__ __align__(16) float g_Wc[2][512];      // combined obs->gate weights
__device__ __align__(16) float g_bc[512];         // combined bias

typedef unsigned long long u64t;

__device__ __forceinline__ u64t fma2(u64t a, u64t b, u64t c) {
    u64t d;
    asm("fma.rn.f32x2 %0, %1, %2, %3;" : "=l"(d) : "l"(a), "l"(b), "l"(c));
    return d;
}
__device__ __forceinline__ u64t pack2(float x) {
    u64t d;
    asm("mov.b64 %0, {%1, %1};" : "=l"(d) : "f"(x));
    return d;
}
__device__ __forceinline__ void unpack2(u64t v, float& lo, float& hi) {
    asm("mov.b64 {%0, %1}, %2;" : "=f"(lo), "=f"(hi) : "l"(v));
}

__device__ __forceinline__ void cp16(void* dst_smem, const void* src) {
    uint32_t d = (uint32_t)__cvta_generic_to_shared(dst_smem);
    asm volatile("cp.async.cg.shared.global [%0], [%1], 16;" :: "r"(d), "l"(src));
}
#define CP_COMMIT() asm volatile("cp.async.commit_group;" ::: "memory")
#define CP_WAIT1()  asm volatile("cp.async.wait_group 1;"  ::: "memory")
#define CP_WAIT0()  asm volatile("cp.async.wait_group 0;"  ::: "memory")

__device__ __forceinline__ float fsig(float x) {
    float e = __expf(-x);
    return __fdividef(1.0f, 1.0f + e);
}
__device__ __forceinline__ float ftanh(float x) {
    x = fminf(fmaxf(x, -15.0f), 15.0f);
    float e = __expf(-2.0f * x);
    return __fdividef(1.0f - e, 1.0f + e);
}

// ---------------------------------------------------------------------------
// Setup: fold embedding into gate weights; transpose W_hh per gate (k-major).
// ---------------------------------------------------------------------------
__global__ void setup_kernel(const float* __restrict__ W_emb, const float* __restrict__ b_emb,
                             const float* __restrict__ W_ih,  const float* __restrict__ W_hh,
                             const float* __restrict__ b_ih,  const float* __restrict__ b_hh) {
    int gid = blockIdx.x * blockDim.x + threadIdx.x;
    if (gid < 4 * 128 * 128) {
        int g = gid >> 14;
        int k = (gid >> 7) & 127;
        int d = gid & 127;
        g_Wt[g][k][d] = W_hh[(g * 128 + d) * 128 + k];
    }
    if (gid < 512) {
        float w0 = 0.f, w1 = 0.f, bb = 0.f;
        #pragma unroll 8
        for (int j = 0; j < 64; ++j) {
            float wij = W_ih[gid * 64 + j];
            w0 += wij * W_emb[j * 2 + 0];
            w1 += wij * W_emb[j * 2 + 1];
            bb += wij * b_emb[j];
        }
        g_Wc[0][gid] = w0;
        g_Wc[1][gid] = w1;
        g_bc[gid]    = bb + b_ih[gid] + b_hh[gid];
    }
}

// ---------------------------------------------------------------------------
// Main fused LSTM kernel (R7 structure, f32x2 pairing over m instead of d).
// Block: 64 batch rows, 256 threads = 32 tx (d-groups of 4) x 8 ty (m-groups of 8).
// acc[g][mp][j] holds the gate pair for (m=mLoc+2mp, m+1) at d=4tx+j:
//   h streams from transposed sH as NATURAL m-pairs (2 LDS.128, zero MOVs);
//   only the 4 per-lane weights need pack2 (8 MOVs/k vs 16 in R7).
// ---------------------------------------------------------------------------
__global__ void __launch_bounds__(THREADS, 1)
lstm_kernel(const float* __restrict__ obs, const float* __restrict__ h0,
            const float* __restrict__ c0, float* __restrict__ out) {
    extern __shared__ float smem[];
    float* sW   = smem + OFF_W;    // 2 x [128][128]  gate-chunk weights, k-major
    float* sH   = smem + OFF_H;    // 2 x [128][HPAD] transposed hidden state
    float* sObs = smem + OFF_OBS;  // [20][2][64]  (component-major for m-pair loads)
    float* sWc  = smem + OFF_WC;   // [2][512]
    float* sBc  = smem + OFF_BC;   // [512]

    const int tid   = threadIdx.x;
    const int tx    = tid & 31;        // d-group: d in [4*tx, 4*tx+4)
    const int ty    = tid >> 5;        // m-group: m in [8*ty, 8*ty+8)
    const int mLoc  = 8 * ty;
    const int mBase = blockIdx.x * M_TILE;

    // --- Stage h0 (transposed), obs ([t][c][m]), combined weights/bias ---
    for (int idx = tid; idx < M_TILE * HID; idx += THREADS) {
        int m = idx >> 7, d = idx & 127;
        sH[d * HPAD + m] = h0[(size_t)(mBase + m) * HID + d];
    }
    for (int idx = tid; idx < T_STEPS * 128; idx += THREADS) {
        int t = idx >> 7, r = idx & 127;
        int c = r >> 6, m = r & 63;
        sObs[idx] = obs[((size_t)t * BATCH + mBase + m) * 2 + c];
    }
    for (int idx = tid; idx < 1024; idx += THREADS) sWc[idx] = (&g_Wc[0][0])[idx];
    for (int idx = tid; idx < 512;  idx += THREADS) sBc[idx] = g_bc[idx];

    // --- c0 into registers: cc[mi][j], m = mLoc+mi, d = 4*tx+j ---
    float cc[8][4];
    #pragma unroll
    for (int mi = 0; mi < 8; ++mi) {
        float4 a = *(const float4*)&c0[(size_t)(mBase + mLoc + mi) * HID + 4 * tx];
        cc[mi][0] = a.x; cc[mi][1] = a.y; cc[mi][2] = a.z; cc[mi][3] = a.w;
    }

    // --- Prefetch gate chunk 0 into weight buffer 0 ---
    {
        const float4* src = (const float4*)&g_Wt[0][0][0];
        float* dst = sW;
        #pragma unroll
        for (int i = 0; i < 16; ++i)
            cp16(dst + (tid + i * 256) * 4, src + tid + i * 256);
        CP_COMMIT();
    }
    __syncthreads();

    int hcur = 0;
    u64t acc[4][4][4]; // [gate][mp][j]: pair (m=mLoc+2mp, m+1), d = 4*tx+j

    for (int t = 0; t < T_STEPS; ++t) {
        // --- init gates: bias + 2-wide obs projection (m-pairs from sObs) ---
        {
            u64t o0[4], o1[4];
            const float* ob = sObs + t * 128 + mLoc;
            #pragma unroll
            for (int mp = 0; mp < 4; ++mp) {
                o0[mp] = *(const u64t*)(ob + 2 * mp);       // comp 0, m-pair
                o1[mp] = *(const u64t*)(ob + 64 + 2 * mp);  // comp 1, m-pair
            }
            #pragma unroll
            for (int g = 0; g < 4; ++g) {
                int n = g * 128 + 4 * tx;
                float4 bv = *(const float4*)&sBc[n];
                float4 wa = *(const float4*)&sWc[n];
                float4 wbv = *(const float4*)&sWc[512 + n];
                u64t bd[4]  = {pack2(bv.x),  pack2(bv.y),  pack2(bv.z),  pack2(bv.w)};
                u64t wdA[4] = {pack2(wa.x),  pack2(wa.y),  pack2(wa.z),  pack2(wa.w)};
                u64t wdB[4] = {pack2(wbv.x), pack2(wbv.y), pack2(wbv.z), pack2(wbv.w)};
                #pragma unroll
                for (int mp = 0; mp < 4; ++mp) {
                    #pragma unroll
                    for (int j = 0; j < 4; ++j)
                        acc[g][mp][j] = fma2(o1[mp], wdB[j], fma2(o0[mp], wdA[j], bd[j]));
                }
            }
        }

        // --- recurrent GEMM: 4 gate chunks, K=128, cp.async double buffered ---
        #pragma unroll
        for (int g = 0; g < 4; ++g) {
            __syncthreads();   // prior chunk's reads done; h writes (prev step) visible
            {
                const float4* src = (const float4*)&g_Wt[(g + 1) & 3][0][0];
                float* dst = sW + ((g + 1) & 1) * 16384;
                #pragma unroll
                for (int i = 0; i < 16; ++i)
                    cp16(dst + (tid + i * 256) * 4, src + tid + i * 256);
                CP_COMMIT();
                CP_WAIT1();    // current chunk's group complete (own thread)
            }
            __syncthreads();   // all threads' cp.async for current chunk visible

            const float* wb = sW + (g & 1) * 16384;
            const float* hb = sH + hcur * HBUF + mLoc;
            #pragma unroll 8
            for (int k = 0; k < 128; ++k) {
                ulonglong2 hA = *(const ulonglong2*)(hb + k * HPAD);      // pairs (m0,m1),(m2,m3)
                ulonglong2 hB = *(const ulonglong2*)(hb + k * HPAD + 4);  // pairs (m4,m5),(m6,m7)
                float4 wv = *(const float4*)(wb + k * 128 + 4 * tx);
                u64t w0 = pack2(wv.x), w1 = pack2(wv.y), w2 = pack2(wv.z), w3 = pack2(wv.w);
                acc[g][0][0] = fma2(hA.x, w0, acc[g][0][0]);
                acc[g][0][1] = fma2(hA.x, w1, acc[g][0][1]);
                acc[g][0][2] = fma2(hA.x, w2, acc[g][0][2]);
                acc[g][0][3] = fma2(hA.x, w3, acc[g][0][3]);
                acc[g][1][0] = fma2(hA.y, w0, acc[g][1][0]);
                acc[g][1][1] = fma2(hA.y, w1, acc[g][1][1]);
                acc[g][1][2] = fma2(hA.y, w2, acc[g][1][2]);
                acc[g][1][3] = fma2(hA.y, w3, acc[g][1][3]);
                acc[g][2][0] = fma2(hB.x, w0, acc[g][2][0]);
                acc[g][2][1] = fma2(hB.x, w1, acc[g][2][1]);
                acc[g][2][2] = fma2(hB.x, w2, acc[g][2][2]);
                acc[g][2][3] = fma2(hB.x, w3, acc[g][2][3]);
                acc[g][3][0] = fma2(hB.y, w0, acc[g][3][0]);
                acc[g][3][1] = fma2(hB.y, w1, acc[g][3][1]);
                acc[g][3][2] = fma2(hB.y, w2, acc[g][3][2]);
                acc[g][3][3] = fma2(hB.y, w3, acc[g][3][3]);
            }
        }

        // --- elementwise LSTM update; write h_new into the other buffer ---
        int hnxt = hcur ^ 1;
        float* hw = sH + hnxt * HBUF;
        #pragma unroll
        for (int mp = 0; mp < 4; ++mp) {
            int m0 = mLoc + 2 * mp;
            #pragma unroll
            for (int j = 0; j < 4; ++j) {
                float i0, i1, f0, f1, g0, g1, o0, o1;
                unpack2(acc[0][mp][j], i0, i1);
                unpack2(acc[1][mp][j], f0, f1);
                unpack2(acc[2][mp][j], g0, g1);
                unpack2(acc[3][mp][j], o0, o1);
                int d = 4 * tx + j;
                {
                    float cn = fsig(f0) * cc[2 * mp][j] + fsig(i0) * ftanh(g0);
                    cc[2 * mp][j] = cn;
                    hw[d * HPAD + m0] = fsig(o0) * ftanh(cn);
                }
                {
                    float cn = fsig(f1) * cc[2 * mp + 1][j] + fsig(i1) * ftanh(g1);
                    cc[2 * mp + 1][j] = cn;
                    hw[d * HPAD + m0 + 1] = fsig(o1) * ftanh(cn);
                }
            }
        }
        hcur = hnxt;
        // next iteration's first __syncthreads orders these writes before reads
    }

    CP_WAIT0();
    __syncthreads();

    // --- write final h (coalesced along d) ---
    const float* hf = sH + hcur * HBUF;
    for (int idx = tid; idx < M_TILE * HID; idx += THREADS) {
        int m = idx >> 7, d = idx & 127;
        out[(size_t)(mBase + m) * HID + d] = hf[d * HPAD + m];
    }
}

extern "C" void kernel_launch(void* const* d_in, const int* in_sizes, int n_in,
                              void* d_out, int out_size) {
    const float* obs   = (const float*)d_in[0];
    const float* h0    = (const float*)d_in[1];
    const float* c0    = (const float*)d_in[2];
    const float* W_emb = (const float*)d_in[3];
    const float* b_emb = (const float*)d_in[4];
    const float* W_ih  = (const float*)d_in[5];
    const float* W_hh  = (const float*)d_in[6];
    const float* b_ih  = (const float*)d_in[7];
    const float* b_hh  = (const float*)d_in[8];
    float* out = (float*)d_out;

    (void)in_sizes; (void)n_in; (void)out_size;

    setup_kernel<<<256, 256>>>(W_emb, b_emb, W_ih, W_hh, b_ih, b_hh);

    cudaFuncSetAttribute(lstm_kernel, cudaFuncAttributeMaxDynamicSharedMemorySize, SMEM_BYTES);
    lstm_kernel<<<BATCH / M_TILE, THREADS, SMEM_BYTES>>>(obs, h0, c0, out);
}